// round 5
// baseline (speedup 1.0000x reference)
#include <cuda_runtime.h>
#include <cstdint>

// CRF Viterbi decode: B=128, T=1024, K=128
// out[b,t,k] = one_hot(tags[b,t]) fp32
//
// 1 CTA/batch. Warp 0 runs the serial Viterbi recurrence with exact candidate
// pruning (batched, branchless, shfl-broadcast state); warps 1-3 stage the
// logit stream through a double-buffered smem ring to hide DRAM latency.

static constexpr int B_ = 128;
static constexpr int T_ = 1024;
static constexpr int K_ = 128;
static constexpr int CHUNK = 16;                      // rows per ring buffer

// Shared memory layout (in 4-byte words)
static constexpr int TT_WORDS  = K_ * K_;             // 16384 row-major transitions
static constexpr int RMIN_OFF  = TT_WORDS;            // 16384
static constexpr int RMAX_OFF  = RMIN_OFF + K_;       // 16512
static constexpr int TAGS_OFF  = RMAX_OFF + K_;       // 16640
static constexpr int BP_OFF    = TAGS_OFF + T_;       // 17664 (u32/(t,lane): 4 packed u8 bp)
static constexpr int RING_OFF  = BP_OFF + T_ * 32;    // 50432 (2 x CHUNK x 128 floats)
static constexpr int SMEM_WORDS = RING_OFF + 2 * CHUNK * K_;  // 54528
static constexpr size_t SMEM_BYTES = (size_t)SMEM_WORDS * 4;  // 218112 B

// Monotone fp32 <-> ordered signed-int key (order-preserving bijection)
__device__ __forceinline__ int f2key(float x) {
    int i = __float_as_int(x);
    return i ^ ((i >> 31) & 0x7fffffff);
}
__device__ __forceinline__ float key2f(int k) {
    return __int_as_float(k ^ ((k >> 31) & 0x7fffffff));
}

// Extract lowest set bit position from 128-bit mask (A:H), branchless; clears it.
// Bit p: q = p>>5, cl = p&31, tag i = 4*cl + q.
__device__ __forceinline__ int ext128(unsigned long long& A, unsigned long long& H) {
    bool ua = (A != 0ull);
    int  pa = __ffsll((long long)A) - 1;
    int  ph = 63 + __ffsll((long long)H);
    int  p  = ua ? pa : ph;
    unsigned long long A2 = A & (A - 1ull);
    unsigned long long H2 = H & (H - 1ull);
    A = ua ? A2 : A;
    H = ua ? H : H2;
    return p;
}

// Exact composite argmax merge: max value, smallest index on ties.
__device__ __forceinline__ void cmerge(float va, int ia, float vb, int ib,
                                       float& vo, int& io) {
    bool g = (vb > va) || (vb == va && ib < ia);
    vo = g ? vb : va;
    io = g ? ib : ia;
}

__global__ void __launch_bounds__(128, 1)
viterbi_kernel(const float* __restrict__ logits,
               const int*   __restrict__ lens,
               const float* __restrict__ trans,
               float*       __restrict__ out)
{
    extern __shared__ float sm[];
    float*    Tt    = sm;
    float*    rminS = sm + RMIN_OFF;
    float*    rmaxS = sm + RMAX_OFF;
    int*      tagsS = (int*)(sm + TAGS_OFF);
    unsigned* bpS   = (unsigned*)(sm + BP_OFF);
    float4*   ring4 = (float4*)(sm + RING_OFF);       // [2][CHUNK][32] float4

    const int b    = blockIdx.x;
    const int tid  = threadIdx.x;
    const int lane = tid & 31;
    const int warp = tid >> 5;
    const unsigned F = 0xffffffffu;

    int L = lens[b];
    L = L < 1 ? 1 : (L > T_ ? T_ : L);
    const float*  lg  = logits + (size_t)b * T_ * K_;
    const float4* lg4 = (const float4*)lg;            // index: t*32 + c

    // ---- Prologue: transitions -> smem, row-major (coalesced LDG.128/STS.128) ----
    {
        const float4* t4g = (const float4*)trans;
        float4*       d4  = (float4*)Tt;
        for (int i = tid; i < (K_ * K_) / 4; i += 128) d4[i] = t4g[i];
    }
    __syncthreads();

    // ---- Per-row min/max (thread = row; rotated column order -> conflict-free) ----
    {
        const float4* rowp = (const float4*)(Tt + tid * K_);
        float mn = __int_as_float(0x7f800000);
        float mx = __int_as_float(0xff800000);
        #pragma unroll
        for (int c0 = 0; c0 < 32; ++c0) {
            int c = (c0 + tid) & 31;
            float4 v = rowp[c];
            mn = fminf(mn, fminf(fminf(v.x, v.y), fminf(v.z, v.w)));
            mx = fmaxf(mx, fmaxf(fmaxf(v.x, v.y), fmaxf(v.z, v.w)));
        }
        rminS[tid] = mn;
        rmaxS[tid] = mx;
    }

    // ---- Prefill ring buffer 0 with logit rows [1, 1+CHUNK) (producers) ----
    if (warp != 0) {
        int ptid = tid - 32;                          // 0..95
        for (int i = ptid; i < CHUNK * 32; i += 96) {
            int r = 1 + (i >> 5); r = r < T_ ? r : T_ - 1;
            ring4[i] = lg4[r * 32 + (i & 31)];
        }
    }
    __syncthreads();

    // Persistent warp-0 registers
    float s[4], rmn[4], rmx[4];
    if (warp == 0) {
        float4 rmn4 = ((const float4*)rminS)[lane];
        float4 rmx4 = ((const float4*)rmaxS)[lane];
        rmn[0]=rmn4.x; rmn[1]=rmn4.y; rmn[2]=rmn4.z; rmn[3]=rmn4.w;
        rmx[0]=rmx4.x; rmx[1]=rmx4.y; rmx[2]=rmx4.z; rmx[3]=rmx4.w;
        float4 v0 = lg4[lane];                        // t=0 logits = init state
        s[0]=v0.x; s[1]=v0.y; s[2]=v0.z; s[3]=v0.w;
    }

    const float4* Trow4 = (const float4*)Tt;          // index: i*32 + lane

    // ---- Chunked forward loop: producers stage chunk ci+1 while warp 0 eats ci ----
    const int nchunks = (L + CHUNK - 2) / CHUNK;      // ceil((L-1)/CHUNK)
    for (int ci = 0; ci < nchunks; ++ci) {
        const int base = 1 + ci * CHUNK;

        if (warp != 0) {
            // stage logit rows [base+CHUNK, base+2*CHUNK) into the other buffer
            int ptid = tid - 32;
            float4* dst = ring4 + ((ci + 1) & 1) * (CHUNK * 32);
            int nb = base + CHUNK;
            #pragma unroll 2
            for (int i = ptid; i < CHUNK * 32; i += 96) {
                int r = nb + (i >> 5); r = r < T_ ? r : T_ - 1;
                dst[i] = lg4[r * 32 + (i & 31)];
            }
        } else {
            const float4* src = ring4 + (ci & 1) * (CHUNK * 32);
            int tend = base + CHUNK < L ? base + CHUNK : L;
            for (int t = base; t < tend; ++t) {
                float4 cl = src[(t - base) * 32 + lane];   // logit row t (smem)

                // ---- LB key = max over all tags of key(s + rowmin) ----
                int k0 = f2key(s[0] + rmn[0]);
                int k1 = f2key(s[1] + rmn[1]);
                int k2 = f2key(s[2] + rmn[2]);
                int k3 = f2key(s[3] + rmn[3]);
                int lm  = max(max(k0, k1), max(k2, k3));
                int kLB = __reduce_max_sync(F, lm);

                // ---- candidate rows: key(s + rowmax) >= kLB ----
                unsigned m0 = __ballot_sync(F, f2key(s[0] + rmx[0]) >= kLB);
                unsigned m1 = __ballot_sync(F, f2key(s[1] + rmx[1]) >= kLB);
                unsigned m2 = __ballot_sync(F, f2key(s[2] + rmx[2]) >= kLB);
                unsigned m3 = __ballot_sync(F, f2key(s[3] + rmx[3]) >= kLB);

                unsigned long long A = (unsigned long long)m0 | ((unsigned long long)m1 << 32);
                unsigned long long H = (unsigned long long)m2 | ((unsigned long long)m3 << 32);
                int n = __popcll(A) + __popcll(H);     // >= 1 always

                // ---- extract up to 4 candidates, branchless; pad with p0 ----
                int p0 = ext128(A, H);
                int p1 = ext128(A, H);
                int p2 = ext128(A, H);
                int p3 = ext128(A, H);
                p1 = (n > 1) ? p1 : p0;
                p2 = (n > 2) ? p2 : p0;
                p3 = (n > 3) ? p3 : p0;

                // state broadcast: uniform q-select on own regs, then SHFL from owner lane
                int cl0 = p0 & 31, q0 = p0 >> 5, i0c = 4 * cl0 + q0;
                int cl1 = p1 & 31, q1 = p1 >> 5, i1c = 4 * cl1 + q1;
                int cl2 = p2 & 31, q2 = p2 >> 5, i2c = 4 * cl2 + q2;
                int cl3 = p3 & 31, q3 = p3 >> 5, i3c = 4 * cl3 + q3;

                float v0s = q0 == 0 ? s[0] : q0 == 1 ? s[1] : q0 == 2 ? s[2] : s[3];
                float v1s = q1 == 0 ? s[0] : q1 == 1 ? s[1] : q1 == 2 ? s[2] : s[3];
                float v2s = q2 == 0 ? s[0] : q2 == 1 ? s[1] : q2 == 2 ? s[2] : s[3];
                float v3s = q3 == 0 ? s[0] : q3 == 1 ? s[1] : q3 == 2 ? s[2] : s[3];
                float sc0 = __shfl_sync(F, v0s, cl0);
                float sc1 = __shfl_sync(F, v1s, cl1);
                float sc2 = __shfl_sync(F, v2s, cl2);
                float sc3 = __shfl_sync(F, v3s, cl3);

                // all 4 transition-row loads issued in parallel (one latency)
                float4 tr0 = Trow4[i0c * 32 + lane];
                float4 tr1 = Trow4[i1c * 32 + lane];
                float4 tr2 = Trow4[i2c * 32 + lane];
                float4 tr3 = Trow4[i3c * 32 + lane];

                // ---- tournament per output slot (exact first-index argmax) ----
                float bv0, bv1, bv2, bv3;  int bi0, bi1, bi2, bi3;
                {
                    float ua, va; int uia, via;
                    cmerge(sc0 + tr0.x, i0c, sc1 + tr1.x, i1c, ua, uia);
                    cmerge(sc2 + tr2.x, i2c, sc3 + tr3.x, i3c, va, via);
                    cmerge(ua, uia, va, via, bv0, bi0);
                    cmerge(sc0 + tr0.y, i0c, sc1 + tr1.y, i1c, ua, uia);
                    cmerge(sc2 + tr2.y, i2c, sc3 + tr3.y, i3c, va, via);
                    cmerge(ua, uia, va, via, bv1, bi1);
                    cmerge(sc0 + tr0.z, i0c, sc1 + tr1.z, i1c, ua, uia);
                    cmerge(sc2 + tr2.z, i2c, sc3 + tr3.z, i3c, va, via);
                    cmerge(ua, uia, va, via, bv2, bi2);
                    cmerge(sc0 + tr0.w, i0c, sc1 + tr1.w, i1c, ua, uia);
                    cmerge(sc2 + tr2.w, i2c, sc3 + tr3.w, i3c, va, via);
                    cmerge(ua, uia, va, via, bv3, bi3);
                }

                // ---- rare overflow: finish remaining candidates serially ----
                if (n > 4) {
                    while (A | H) {
                        int p = ext128(A, H);
                        int clr = p & 31, qr = p >> 5, ir = 4 * clr + qr;
                        float vr = qr == 0 ? s[0] : qr == 1 ? s[1] : qr == 2 ? s[2] : s[3];
                        float scr = __shfl_sync(F, vr, clr);
                        float4 trr = Trow4[ir * 32 + lane];
                        cmerge(bv0, bi0, scr + trr.x, ir, bv0, bi0);
                        cmerge(bv1, bi1, scr + trr.y, ir, bv1, bi1);
                        cmerge(bv2, bi2, scr + trr.z, ir, bv2, bi2);
                        cmerge(bv3, bi3, scr + trr.w, ir, bv3, bi3);
                    }
                }

                s[0] = bv0 + cl.x;
                s[1] = bv1 + cl.y;
                s[2] = bv2 + cl.z;
                s[3] = bv3 + cl.w;

                bpS[t * 32 + lane] = (unsigned)bi0 | ((unsigned)bi1 << 8) |
                                     ((unsigned)bi2 << 16) | ((unsigned)bi3 << 24);
            }
        }
        __syncthreads();   // chunk handoff: ring slot (ci+1) full, slot ci free
    }

    if (warp == 0) {
        // ---- last_tag = first argmax of final state ----
        float fm = fmaxf(fmaxf(s[0], s[1]), fmaxf(s[2], s[3]));
        int   mk = __reduce_max_sync(F, f2key(fm));
        float M  = key2f(mk);
        unsigned cand = 0x7fffffffu;
        #pragma unroll
        for (int q = 0; q < 4; ++q) {
            unsigned tg = (unsigned)(4 * lane + q);
            cand = (s[q] == M && tg < cand) ? tg : cand;
        }
        int last = (int)__reduce_min_sync(F, cand);

        // tags[t] = last for t in [L-1, T)  (bp is identity past L)
        for (int t = L - 1 + lane; t < T_; t += 32) tagsS[t] = last;

        // ---- backtrack: byte-addressed LDS chain (bp byte for tag i at t*128+i) ----
        if (lane == 0) {
            const unsigned char* bpB = (const unsigned char*)bpS;
            int cur = last;
            for (int t = L - 1; t >= 1; --t) {
                cur = bpB[t * 128 + cur];
                tagsS[t - 1] = cur;
            }
        }
    }
    __syncthreads();

    // ---- one-hot epilogue: 512 KB per CTA, coalesced STG.128 ----
    float4* out4 = (float4*)(out + (size_t)b * T_ * K_);
    for (int idx = tid; idx < T_ * (K_ / 4); idx += 128) {
        int t = idx >> 5;
        int c = (idx & 31) * 4;
        int tag = tagsS[t];
        float4 v;
        v.x = (tag == c    ) ? 1.f : 0.f;
        v.y = (tag == c + 1) ? 1.f : 0.f;
        v.z = (tag == c + 2) ? 1.f : 0.f;
        v.w = (tag == c + 3) ? 1.f : 0.f;
        out4[idx] = v;
    }
}

extern "C" void kernel_launch(void* const* d_in, const int* in_sizes, int n_in,
                              void* d_out, int out_size)
{
    const float* logits = (const float*)d_in[0];
    const int*   lens   = (const int*)d_in[1];
    const float* trans  = (const float*)d_in[2];
    float*       out    = (float*)d_out;

    cudaFuncSetAttribute(viterbi_kernel,
                         cudaFuncAttributeMaxDynamicSharedMemorySize,
                         (int)SMEM_BYTES);
    viterbi_kernel<<<B_, 128, SMEM_BYTES>>>(logits, lens, trans, out);
}

// round 7
// speedup vs baseline: 1.3930x; 1.3930x over previous
#include <cuda_runtime.h>
#include <cstdint>

// CRF Viterbi decode: B=128, T=1024, K=128
// out[b,t,k] = one_hot(tags[b,t]) fp32
//
// 1 CTA/batch. Warp 0 runs the serial Viterbi recurrence with exact candidate
// pruning; warps 1-3 stage the logit stream through a double-buffered smem
// ring to hide DRAM latency. 2-wide branchless candidate handling with
// shfl-broadcast state; bound operands precomputed in the latency shadow.

static constexpr int B_ = 128;
static constexpr int T_ = 1024;
static constexpr int K_ = 128;
static constexpr int CHUNK = 16;                      // rows per ring buffer

// Shared memory layout (in 4-byte words)
static constexpr int TT_WORDS  = K_ * K_;             // 16384 row-major transitions
static constexpr int RMIN_OFF  = TT_WORDS;            // 16384
static constexpr int RMAX_OFF  = RMIN_OFF + K_;       // 16512
static constexpr int TAGS_OFF  = RMAX_OFF + K_;       // 16640
static constexpr int BP_OFF    = TAGS_OFF + T_;       // 17664 (u32/(t,lane): 4 packed u8 bp)
static constexpr int RING_OFF  = BP_OFF + T_ * 32;    // 50432 (2 x CHUNK x 128 floats)
static constexpr int SMEM_WORDS = RING_OFF + 2 * CHUNK * K_;  // 54528
static constexpr size_t SMEM_BYTES = (size_t)SMEM_WORDS * 4;  // 218112 B

// Monotone fp32 <-> ordered signed-int key (order-preserving bijection)
__device__ __forceinline__ int f2key(float x) {
    int i = __float_as_int(x);
    return i ^ ((i >> 31) & 0x7fffffff);
}
__device__ __forceinline__ float key2f(int k) {
    return __int_as_float(k ^ ((k >> 31) & 0x7fffffff));
}

// Extract lowest set bit position from 128-bit mask (A:H), branchless; clears it.
// Bit p: q = p>>5, cl = p&31, tag i = 4*cl + q.
__device__ __forceinline__ int ext128(unsigned long long& A, unsigned long long& H) {
    bool ua = (A != 0ull);
    int  pa = __ffsll((long long)A) - 1;
    int  ph = 63 + __ffsll((long long)H);
    int  p  = ua ? pa : ph;
    unsigned long long A2 = A & (A - 1ull);
    unsigned long long H2 = H & (H - 1ull);
    A = ua ? A2 : A;
    H = ua ? H : H2;
    return p;
}

// Exact composite argmax merge: max value, smallest index on ties.
__device__ __forceinline__ void cmerge(float va, int ia, float vb, int ib,
                                       float& vo, int& io) {
    bool g = (vb > va) || (vb == va && ib < ia);
    vo = g ? vb : va;
    io = g ? ib : ia;
}

__global__ void __launch_bounds__(128, 1)
viterbi_kernel(const float* __restrict__ logits,
               const int*   __restrict__ lens,
               const float* __restrict__ trans,
               float*       __restrict__ out)
{
    extern __shared__ float sm[];
    float*    Tt    = sm;
    float*    rminS = sm + RMIN_OFF;
    float*    rmaxS = sm + RMAX_OFF;
    int*      tagsS = (int*)(sm + TAGS_OFF);
    unsigned* bpS   = (unsigned*)(sm + BP_OFF);
    float4*   ring4 = (float4*)(sm + RING_OFF);       // [2][CHUNK][32] float4

    const int b    = blockIdx.x;
    const int tid  = threadIdx.x;
    const int lane = tid & 31;
    const int warp = tid >> 5;
    const unsigned F = 0xffffffffu;

    int L = lens[b];
    L = L < 1 ? 1 : (L > T_ ? T_ : L);
    const float*  lg  = logits + (size_t)b * T_ * K_;
    const float4* lg4 = (const float4*)lg;            // index: t*32 + c

    // ---- Prologue: transitions -> smem, row-major (coalesced LDG.128/STS.128) ----
    {
        const float4* t4g = (const float4*)trans;
        float4*       d4  = (float4*)Tt;
        for (int i = tid; i < (K_ * K_) / 4; i += 128) d4[i] = t4g[i];
    }
    __syncthreads();

    // ---- Per-row min/max (thread = row; rotated column order -> conflict-free) ----
    {
        const float4* rowp = (const float4*)(Tt + tid * K_);
        float mn = __int_as_float(0x7f800000);
        float mx = __int_as_float(0xff800000);
        #pragma unroll
        for (int c0 = 0; c0 < 32; ++c0) {
            int c = (c0 + tid) & 31;
            float4 v = rowp[c];
            mn = fminf(mn, fminf(fminf(v.x, v.y), fminf(v.z, v.w)));
            mx = fmaxf(mx, fmaxf(fmaxf(v.x, v.y), fmaxf(v.z, v.w)));
        }
        rminS[tid] = mn;
        rmaxS[tid] = mx;
    }

    // ---- Prefill ring buffer 0 with logit rows [1, 1+CHUNK) (producers) ----
    if (warp != 0) {
        int ptid = tid - 32;                          // 0..95
        for (int i = ptid; i < CHUNK * 32; i += 96) {
            int r = 1 + (i >> 5); r = r < T_ ? r : T_ - 1;
            ring4[i] = lg4[r * 32 + (i & 31)];
        }
    }
    __syncthreads();

    // Persistent warp-0 registers.
    // an[q] = s[q] + rmn[q], ax[q] = s[q] + rmx[q] -- maintained one FADD off s,
    // computed in the latency shadow of the previous step's tail.
    float s[4], an[4], ax[4], rmn[4], rmx[4];
    if (warp == 0) {
        float4 rmn4 = ((const float4*)rminS)[lane];
        float4 rmx4 = ((const float4*)rmaxS)[lane];
        rmn[0]=rmn4.x; rmn[1]=rmn4.y; rmn[2]=rmn4.z; rmn[3]=rmn4.w;
        rmx[0]=rmx4.x; rmx[1]=rmx4.y; rmx[2]=rmx4.z; rmx[3]=rmx4.w;
        float4 v0 = lg4[lane];                        // t=0 logits = init state
        s[0]=v0.x; s[1]=v0.y; s[2]=v0.z; s[3]=v0.w;
        #pragma unroll
        for (int q = 0; q < 4; ++q) { an[q] = s[q] + rmn[q]; ax[q] = s[q] + rmx[q]; }
    }

    const float4* Trow4 = (const float4*)Tt;          // index: i*32 + lane

    // ---- Chunked forward loop: producers stage chunk ci+1 while warp 0 eats ci ----
    const int nchunks = (L + CHUNK - 2) / CHUNK;      // ceil((L-1)/CHUNK)
    for (int ci = 0; ci < nchunks; ++ci) {
        const int base = 1 + ci * CHUNK;

        if (warp != 0) {
            // stage logit rows [base+CHUNK, base+2*CHUNK) into the other buffer
            int ptid = tid - 32;
            float4* dst = ring4 + ((ci + 1) & 1) * (CHUNK * 32);
            int nb = base + CHUNK;
            #pragma unroll 2
            for (int i = ptid; i < CHUNK * 32; i += 96) {
                int r = nb + (i >> 5); r = r < T_ ? r : T_ - 1;
                dst[i] = lg4[r * 32 + (i & 31)];
            }
        } else {
            const float4* src = ring4 + (ci & 1) * (CHUNK * 32);
            int tend = base + CHUNK < L ? base + CHUNK : L;
            for (int t = base; t < tend; ++t) {
                // logit row t (smem ring) -- needed only at the tail of the chain
                float4 clt = src[(t - base) * 32 + lane];

                // ---- LB: kLB = REDUX max key(s + rowmin)  (exact, monotone) ----
                float am  = fmaxf(fmaxf(an[0], an[1]), fmaxf(an[2], an[3]));
                int   kLB = __reduce_max_sync(F, f2key(am));

                // ballot operand keys computed in the REDUX latency shadow
                int u0 = f2key(ax[0]);
                int u1 = f2key(ax[1]);
                int u2 = f2key(ax[2]);
                int u3 = f2key(ax[3]);

                unsigned m0 = __ballot_sync(F, u0 >= kLB);
                unsigned m1 = __ballot_sync(F, u1 >= kLB);
                unsigned m2 = __ballot_sync(F, u2 >= kLB);
                unsigned m3 = __ballot_sync(F, u3 >= kLB);

                unsigned long long A = (unsigned long long)m0 | ((unsigned long long)m1 << 32);
                unsigned long long H = (unsigned long long)m2 | ((unsigned long long)m3 << 32);
                int n = __popcll(A) + __popcll(H);     // >= 1 always

                // ---- 2-wide branchless candidate handling (covers n <= 2) ----
                int p0 = ext128(A, H);
                int p1t = ext128(A, H);
                int p1 = (n > 1) ? p1t : p0;

                int c0l = p0 & 31, q0 = p0 >> 5, i0c = 4 * c0l + q0;
                int c1l = p1 & 31, q1 = p1 >> 5, i1c = 4 * c1l + q1;

                float w0 = q0 == 0 ? s[0] : q0 == 1 ? s[1] : q0 == 2 ? s[2] : s[3];
                float w1 = q1 == 0 ? s[0] : q1 == 1 ? s[1] : q1 == 2 ? s[2] : s[3];
                float sc0 = __shfl_sync(F, w0, c0l);
                float sc1 = __shfl_sync(F, w1, c1l);

                float4 tr0 = Trow4[i0c * 32 + lane];   // both LDS.128 in flight together
                float4 tr1 = Trow4[i1c * 32 + lane];

                float bv0, bv1, bv2, bv3;  int bi0, bi1, bi2, bi3;
                cmerge(sc0 + tr0.x, i0c, sc1 + tr1.x, i1c, bv0, bi0);
                cmerge(sc0 + tr0.y, i0c, sc1 + tr1.y, i1c, bv1, bi1);
                cmerge(sc0 + tr0.z, i0c, sc1 + tr1.z, i1c, bv2, bi2);
                cmerge(sc0 + tr0.w, i0c, sc1 + tr1.w, i1c, bv3, bi3);

                // ---- rare overflow: remaining candidates serially ----
                if (n > 2) {
                    while (A | H) {
                        int p = ext128(A, H);
                        int clr = p & 31, qr = p >> 5, ir = 4 * clr + qr;
                        float vr = qr == 0 ? s[0] : qr == 1 ? s[1] : qr == 2 ? s[2] : s[3];
                        float scr = __shfl_sync(F, vr, clr);
                        float4 trr = Trow4[ir * 32 + lane];
                        cmerge(bv0, bi0, scr + trr.x, ir, bv0, bi0);
                        cmerge(bv1, bi1, scr + trr.y, ir, bv1, bi1);
                        cmerge(bv2, bi2, scr + trr.z, ir, bv2, bi2);
                        cmerge(bv3, bi3, scr + trr.w, ir, bv3, bi3);
                    }
                }

                // ---- state update + next-step bound operands (latency shadow) ----
                s[0] = bv0 + clt.x;
                s[1] = bv1 + clt.y;
                s[2] = bv2 + clt.z;
                s[3] = bv3 + clt.w;
                an[0] = s[0] + rmn[0]; ax[0] = s[0] + rmx[0];
                an[1] = s[1] + rmn[1]; ax[1] = s[1] + rmx[1];
                an[2] = s[2] + rmn[2]; ax[2] = s[2] + rmx[2];
                an[3] = s[3] + rmn[3]; ax[3] = s[3] + rmx[3];

                bpS[t * 32 + lane] = (unsigned)bi0 | ((unsigned)bi1 << 8) |
                                     ((unsigned)bi2 << 16) | ((unsigned)bi3 << 24);
            }
        }
        __syncthreads();   // chunk handoff: ring slot (ci+1) full, slot ci free
    }

    if (warp == 0) {
        // ---- last_tag = first argmax of final state ----
        float fm = fmaxf(fmaxf(s[0], s[1]), fmaxf(s[2], s[3]));
        int   mk = __reduce_max_sync(F, f2key(fm));
        float M  = key2f(mk);
        unsigned cand = 0x7fffffffu;
        #pragma unroll
        for (int q = 0; q < 4; ++q) {
            unsigned tg = (unsigned)(4 * lane + q);
            cand = (s[q] == M && tg < cand) ? tg : cand;
        }
        int last = (int)__reduce_min_sync(F, cand);

        // tags[t] = last for t in [L-1, T)  (bp is identity past L)
        for (int t = L - 1 + lane; t < T_; t += 32) tagsS[t] = last;

        // ---- backtrack: byte-addressed LDS chain (bp byte for tag i at t*128+i) ----
        if (lane == 0) {
            const unsigned char* bpB = (const unsigned char*)bpS;
            int cur = last;
            for (int t = L - 1; t >= 1; --t) {
                cur = bpB[t * 128 + cur];
                tagsS[t - 1] = cur;
            }
        }
    }
    __syncthreads();

    // ---- one-hot epilogue: 512 KB per CTA, coalesced STG.128 ----
    float4* out4 = (float4*)(out + (size_t)b * T_ * K_);
    for (int idx = tid; idx < T_ * (K_ / 4); idx += 128) {
        int t = idx >> 5;
        int c = (idx & 31) * 4;
        int tag = tagsS[t];
        float4 v;
        v.x = (tag == c    ) ? 1.f : 0.f;
        v.y = (tag == c + 1) ? 1.f : 0.f;
        v.z = (tag == c + 2) ? 1.f : 0.f;
        v.w = (tag == c + 3) ? 1.f : 0.f;
        out4[idx] = v;
    }
}

extern "C" void kernel_launch(void* const* d_in, const int* in_sizes, int n_in,
                              void* d_out, int out_size)
{
    const float* logits = (const float*)d_in[0];
    const int*   lens   = (const int*)d_in[1];
    const float* trans  = (const float*)d_in[2];
    float*       out    = (float*)d_out;

    cudaFuncSetAttribute(viterbi_kernel,
                         cudaFuncAttributeMaxDynamicSharedMemorySize,
                         (int)SMEM_BYTES);
    viterbi_kernel<<<B_, 128, SMEM_BYTES>>>(logits, lens, trans, out);
}